// round 1
// baseline (speedup 1.0000x reference)
#include <cuda_runtime.h>

#define N_NODES   100000
#define N_EDGES   1280000
#define D         64
#define N_GRAPHS  512
#define SCAN_B    1024
#define N_SCANBLK ((N_NODES + SCAN_B - 1) / SCAN_B)   // 98

// ---------------- scratch (device globals; no cudaMalloc allowed) -----------
__device__ float g_h  [N_NODES * D];   // GEMM output (gather source)
__device__ float g_t0 [N_NODES * D];   // layer outputs ping
__device__ float g_t1 [N_NODES * D];   // layer outputs pong
__device__ float g_dinv[N_NODES];
__device__ int   g_dege[N_NODES];      // in-degree (edges only, no self loop)
__device__ int   g_rowstart[N_NODES + 1];
__device__ int   g_cursor[N_NODES];
__device__ int   g_bsums[128];
__device__ int   g_csrc [N_EDGES];
__device__ float g_cnorm[N_EDGES];
__device__ float g_gsum[N_GRAPHS];
__device__ int   g_gcnt[N_GRAPHS];

// ---------------- setup kernels ---------------------------------------------
__global__ void k_zero() {
    int i = blockIdx.x * blockDim.x + threadIdx.x;
    if (i < N_NODES) g_dege[i] = 0;
    if (i < N_GRAPHS) { g_gsum[i] = 0.f; g_gcnt[i] = 0; }
}

__global__ void k_deg(const int* __restrict__ ei) {
    int e = blockIdx.x * blockDim.x + threadIdx.x;
    if (e < N_EDGES) atomicAdd(&g_dege[ei[N_EDGES + e]], 1);
}

__global__ void k_dinv(const int* __restrict__ batch) {
    int i = blockIdx.x * blockDim.x + threadIdx.x;
    if (i < N_NODES) {
        g_dinv[i] = rsqrtf((float)(g_dege[i] + 1));   // +1 self loop
        atomicAdd(&g_gcnt[batch[i]], 1);
    }
}

// per-block inclusive scan of g_dege -> exclusive prefix in g_rowstart
__global__ void k_scan1() {
    __shared__ int sh[SCAN_B];
    int tid = threadIdx.x;
    int i = blockIdx.x * SCAN_B + tid;
    int v = (i < N_NODES) ? g_dege[i] : 0;
    sh[tid] = v;
    __syncthreads();
    for (int off = 1; off < SCAN_B; off <<= 1) {
        int t = 0;
        if (tid >= off) t = sh[tid - off];
        __syncthreads();
        sh[tid] += t;
        __syncthreads();
    }
    int incl = sh[tid];
    if (i < N_NODES) g_rowstart[i] = incl - v;   // exclusive
    if (tid == SCAN_B - 1) g_bsums[blockIdx.x] = incl;
}

__global__ void k_scan2() {
    if (threadIdx.x == 0) {
        int run = 0;
        for (int b = 0; b < N_SCANBLK; b++) {
            int v = g_bsums[b];
            g_bsums[b] = run;
            run += v;
        }
        g_rowstart[N_NODES] = run;   // == N_EDGES
    }
}

__global__ void k_scan3() {
    int i = blockIdx.x * blockDim.x + threadIdx.x;
    if (i < N_NODES) {
        int rs = g_rowstart[i] + g_bsums[i / SCAN_B];
        g_rowstart[i] = rs;
        g_cursor[i] = rs;
    }
}

__global__ void k_fill(const int* __restrict__ ei) {
    int e = blockIdx.x * blockDim.x + threadIdx.x;
    if (e < N_EDGES) {
        int s = ei[e];
        int d = ei[N_EDGES + e];
        int pos = atomicAdd(&g_cursor[d], 1);
        g_csrc[pos]  = s;
        g_cnorm[pos] = g_dinv[s] * g_dinv[d];
    }
}

// ---------------- GEMM: out[row] = in[row] @ W  (100000x64 @ 64x64) ---------
__global__ void __launch_bounds__(128) k_gemm(const float* __restrict__ in,
                                              const float* __restrict__ W,
                                              float* __restrict__ out) {
    __shared__ float ws[D * D];
    int tid = threadIdx.x;
    for (int j = tid; j < (D * D) / 4; j += blockDim.x)
        ((float4*)ws)[j] = ((const float4*)W)[j];
    __syncthreads();

    int row = blockIdx.x * blockDim.x + tid;
    if (row >= N_NODES) return;

    float acc[D];
#pragma unroll
    for (int c = 0; c < D; c++) acc[c] = 0.f;

    const float4* inr = (const float4*)(in + (size_t)row * D);
#pragma unroll 2
    for (int k4 = 0; k4 < D / 4; k4++) {
        float4 xv = inr[k4];
        float xs[4] = {xv.x, xv.y, xv.z, xv.w};
#pragma unroll
        for (int j = 0; j < 4; j++) {
            float xk = xs[j];
            const float4* wrow = (const float4*)(ws + (k4 * 4 + j) * D);
#pragma unroll
            for (int c4 = 0; c4 < D / 4; c4++) {
                float4 w = wrow[c4];
                acc[c4 * 4 + 0] += xk * w.x;
                acc[c4 * 4 + 1] += xk * w.y;
                acc[c4 * 4 + 2] += xk * w.z;
                acc[c4 * 4 + 3] += xk * w.w;
            }
        }
    }
    float4* o = (float4*)(out + (size_t)row * D);
#pragma unroll
    for (int c4 = 0; c4 < D / 4; c4++)
        o[c4] = make_float4(acc[4 * c4], acc[4 * c4 + 1], acc[4 * c4 + 2], acc[4 * c4 + 3]);
}

// ------- gather: out = relu( sum_{e: dst=n} norm_e * h[src_e] + dinv_n^2*h_n + b )
// 16 lanes per node, one float4 accumulator per lane.
__global__ void __launch_bounds__(256) k_gather(const float* __restrict__ h,
                                                const float* __restrict__ b,
                                                float* __restrict__ out) {
    int gt = blockIdx.x * blockDim.x + threadIdx.x;
    int node = gt >> 4;
    int c = gt & 15;
    if (node >= N_NODES) return;

    const float4* h4 = (const float4*)h;
    float di = g_dinv[node];
    float sl = di * di;
    float4 bb = ((const float4*)b)[c];
    float4 a  = h4[(size_t)node * 16 + c];
    float4 acc;
    acc.x = a.x * sl + bb.x;
    acc.y = a.y * sl + bb.y;
    acc.z = a.z * sl + bb.z;
    acc.w = a.w * sl + bb.w;

    int e0 = g_rowstart[node];
    int e1 = g_rowstart[node + 1];
    for (int e = e0; e < e1; e++) {
        int   s  = g_csrc[e];
        float nr = g_cnorm[e];
        float4 v = h4[(size_t)s * 16 + c];
        acc.x += v.x * nr;
        acc.y += v.y * nr;
        acc.z += v.z * nr;
        acc.w += v.w * nr;
    }
    acc.x = fmaxf(acc.x, 0.f);
    acc.y = fmaxf(acc.y, 0.f);
    acc.z = fmaxf(acc.z, 0.f);
    acc.w = fmaxf(acc.w, 0.f);
    ((float4*)out)[(size_t)node * 16 + c] = acc;
}

// ------- pool: per-node dot with fc_w, scalar atomic into per-graph sum -----
__global__ void __launch_bounds__(256) k_pool(const float* __restrict__ hfin,
                                              const float* __restrict__ fcw,
                                              const int* __restrict__ batch) {
    __shared__ float w[D];
    if (threadIdx.x < D) w[threadIdx.x] = fcw[threadIdx.x];
    __syncthreads();
    int i = blockIdx.x * blockDim.x + threadIdx.x;
    if (i >= N_NODES) return;
    const float4* r = (const float4*)(hfin + (size_t)i * D);
    float s = 0.f;
#pragma unroll
    for (int c4 = 0; c4 < D / 4; c4++) {
        float4 v = r[c4];
        s += v.x * w[c4 * 4 + 0] + v.y * w[c4 * 4 + 1]
           + v.z * w[c4 * 4 + 2] + v.w * w[c4 * 4 + 3];
    }
    atomicAdd(&g_gsum[batch[i]], s);
}

__global__ void k_final(float* __restrict__ out, const float* __restrict__ fcb) {
    int g = blockIdx.x * blockDim.x + threadIdx.x;
    if (g < N_GRAPHS)
        out[g] = g_gsum[g] / fmaxf((float)g_gcnt[g], 1.f) + fcb[0];
}

// ---------------- launch ------------------------------------------------------
extern "C" void kernel_launch(void* const* d_in, const int* in_sizes, int n_in,
                              void* d_out, int out_size) {
    const float* x     = (const float*)d_in[0];
    const int*   ei    = (const int*)  d_in[1];
    const int*   batch = (const int*)  d_in[2];
    const float* w0    = (const float*)d_in[3];
    const float* b0    = (const float*)d_in[4];
    const float* w1    = (const float*)d_in[5];
    const float* b1    = (const float*)d_in[6];
    const float* w2    = (const float*)d_in[7];
    const float* b2    = (const float*)d_in[8];
    const float* fcw   = (const float*)d_in[9];
    const float* fcb   = (const float*)d_in[10];
    float* out = (float*)d_out;

    float *h, *t0, *t1;
    cudaGetSymbolAddress((void**)&h,  g_h);
    cudaGetSymbolAddress((void**)&t0, g_t0);
    cudaGetSymbolAddress((void**)&t1, g_t1);

    const int TB = 256;
    int nb_nodes = (N_NODES + TB - 1) / TB;       // 391
    int nb_edges = (N_EDGES + TB - 1) / TB;       // 5000
    int nb_gemm  = (N_NODES + 127) / 128;         // 782
    int nb_gath  = (N_NODES * 16 + TB - 1) / TB;  // 6250

    // CSR build (once per call, reused by all 3 layers)
    k_zero <<<nb_nodes, TB>>>();
    k_deg  <<<nb_edges, TB>>>(ei);
    k_dinv <<<nb_nodes, TB>>>(batch);
    k_scan1<<<N_SCANBLK, SCAN_B>>>();
    k_scan2<<<1, 32>>>();
    k_scan3<<<nb_nodes, TB>>>();
    k_fill <<<nb_edges, TB>>>(ei);

    // layer 1
    k_gemm  <<<nb_gemm, 128>>>(x, w0, h);
    k_gather<<<nb_gath, TB>>>(h, b0, t0);
    // layer 2
    k_gemm  <<<nb_gemm, 128>>>(t0, w1, h);
    k_gather<<<nb_gath, TB>>>(h, b1, t1);
    // layer 3
    k_gemm  <<<nb_gemm, 128>>>(t1, w2, h);
    k_gather<<<nb_gath, TB>>>(h, b2, t0);

    // pool + head
    k_pool <<<nb_nodes, TB>>>(t0, fcw, batch);
    k_final<<<(N_GRAPHS + TB - 1) / TB, TB>>>(out, fcb);
}

// round 2
// speedup vs baseline: 1.1634x; 1.1634x over previous
#include <cuda_runtime.h>
#include <cuda_fp16.h>

#define N_NODES   100000
#define N_EDGES   1280000
#define D         64
#define N_GRAPHS  512
#define SCAN_B    1024
#define N_SCANBLK ((N_NODES + SCAN_B - 1) / SCAN_B)   // 98

// ---------------- scratch (device globals; no cudaMalloc allowed) -----------
__device__ __half g_h  [N_NODES * D];   // GEMM output, pre-scaled by dinv[row]
__device__ __half g_t0 [N_NODES * D];   // layer outputs ping
__device__ __half g_t1 [N_NODES * D];   // layer outputs pong
__device__ float  g_dinv[N_NODES];
__device__ int    g_dege[N_NODES];      // in-degree (edges only, no self loop)
__device__ int    g_rowstart[N_NODES + 1];
__device__ int    g_cursor[N_NODES];
__device__ int    g_bsums[128];
__device__ int    g_csrc [N_EDGES];
__device__ float  g_gsum[N_GRAPHS];
__device__ int    g_gcnt[N_GRAPHS];

// ---------------- setup kernels ---------------------------------------------
__global__ void k_zero() {
    int i = blockIdx.x * blockDim.x + threadIdx.x;
    if (i < N_NODES) g_dege[i] = 0;
    if (i < N_GRAPHS) { g_gsum[i] = 0.f; g_gcnt[i] = 0; }
}

__global__ void k_deg(const int* __restrict__ ei) {
    int e = blockIdx.x * blockDim.x + threadIdx.x;
    if (e < N_EDGES) atomicAdd(&g_dege[ei[N_EDGES + e]], 1);
}

// per-block inclusive scan of g_dege -> exclusive prefix in g_rowstart
__global__ void k_scan1() {
    __shared__ int sh[SCAN_B];
    int tid = threadIdx.x;
    int i = blockIdx.x * SCAN_B + tid;
    int v = (i < N_NODES) ? g_dege[i] : 0;
    sh[tid] = v;
    __syncthreads();
    for (int off = 1; off < SCAN_B; off <<= 1) {
        int t = 0;
        if (tid >= off) t = sh[tid - off];
        __syncthreads();
        sh[tid] += t;
        __syncthreads();
    }
    int incl = sh[tid];
    if (i < N_NODES) g_rowstart[i] = incl - v;   // exclusive
    if (tid == SCAN_B - 1) g_bsums[blockIdx.x] = incl;
}

__global__ void k_scan2() {
    if (threadIdx.x == 0) {
        int run = 0;
        for (int b = 0; b < N_SCANBLK; b++) {
            int v = g_bsums[b];
            g_bsums[b] = run;
            run += v;
        }
        g_rowstart[N_NODES] = run;   // == N_EDGES
    }
}

// finalize rowstart/cursor + compute dinv + graph counts (fused)
__global__ void k_scan3(const int* __restrict__ batch) {
    int i = blockIdx.x * blockDim.x + threadIdx.x;
    if (i < N_NODES) {
        int rs = g_rowstart[i] + g_bsums[i / SCAN_B];
        g_rowstart[i] = rs;
        g_cursor[i] = rs;
        g_dinv[i] = rsqrtf((float)(g_dege[i] + 1));   // +1 self loop
        atomicAdd(&g_gcnt[batch[i]], 1);
    }
}

__global__ void k_fill(const int* __restrict__ ei) {
    int e = blockIdx.x * blockDim.x + threadIdx.x;
    if (e < N_EDGES) {
        int s = ei[e];
        int d = ei[N_EDGES + e];
        int pos = atomicAdd(&g_cursor[d], 1);
        g_csrc[pos] = s;
    }
}

// ---------------- GEMM: out[row] = dinv[row] * (in[row] @ W), fp16 out -------
__device__ __forceinline__ void fetch4(const float* __restrict__ p, int k4, float xs[4]) {
    float4 v = ((const float4*)p)[k4];
    xs[0] = v.x; xs[1] = v.y; xs[2] = v.z; xs[3] = v.w;
}
__device__ __forceinline__ void fetch4(const __half* __restrict__ p, int k4, float xs[4]) {
    uint2 v = ((const uint2*)p)[k4];
    __half2 lo = *(__half2*)&v.x;
    __half2 hi = *(__half2*)&v.y;
    float2 flo = __half22float2(lo);
    float2 fhi = __half22float2(hi);
    xs[0] = flo.x; xs[1] = flo.y; xs[2] = fhi.x; xs[3] = fhi.y;
}

template <typename TIN>
__global__ void __launch_bounds__(128) k_gemm(const TIN* __restrict__ in,
                                              const float* __restrict__ W,
                                              __half* __restrict__ out) {
    __shared__ float ws[D * D];
    int tid = threadIdx.x;
    for (int j = tid; j < (D * D) / 4; j += blockDim.x)
        ((float4*)ws)[j] = ((const float4*)W)[j];
    __syncthreads();

    int row = blockIdx.x * blockDim.x + tid;
    if (row >= N_NODES) return;

    float acc[D];
#pragma unroll
    for (int c = 0; c < D; c++) acc[c] = 0.f;

    const TIN* inr = in + (size_t)row * D;
#pragma unroll 2
    for (int k4 = 0; k4 < D / 4; k4++) {
        float xs[4];
        fetch4(inr, k4, xs);
#pragma unroll
        for (int j = 0; j < 4; j++) {
            float xk = xs[j];
            const float4* wrow = (const float4*)(ws + (k4 * 4 + j) * D);
#pragma unroll
            for (int c4 = 0; c4 < D / 4; c4++) {
                float4 w = wrow[c4];
                acc[c4 * 4 + 0] += xk * w.x;
                acc[c4 * 4 + 1] += xk * w.y;
                acc[c4 * 4 + 2] += xk * w.z;
                acc[c4 * 4 + 3] += xk * w.w;
            }
        }
    }

    float s = g_dinv[row];
    uint4* orow = (uint4*)(out + (size_t)row * D);
#pragma unroll
    for (int q = 0; q < 8; q++) {
        __half2 p0 = __floats2half2_rn(acc[8 * q + 0] * s, acc[8 * q + 1] * s);
        __half2 p1 = __floats2half2_rn(acc[8 * q + 2] * s, acc[8 * q + 3] * s);
        __half2 p2 = __floats2half2_rn(acc[8 * q + 4] * s, acc[8 * q + 5] * s);
        __half2 p3 = __floats2half2_rn(acc[8 * q + 6] * s, acc[8 * q + 7] * s);
        uint4 u;
        u.x = *(unsigned*)&p0; u.y = *(unsigned*)&p1;
        u.z = *(unsigned*)&p2; u.w = *(unsigned*)&p3;
        orow[q] = u;
    }
}

// ------- gather: out = relu( dinv_n * (sum_{e: dst=n} h'[src_e] + h'[n]) + b )
// 16 lanes per node, each lane owns 4 channels (8 bytes fp16), fp32 accumulate.
__device__ __forceinline__ float4 h4_to_f4(uint2 v) {
    __half2 lo = *(__half2*)&v.x;
    __half2 hi = *(__half2*)&v.y;
    float2 flo = __half22float2(lo);
    float2 fhi = __half22float2(hi);
    return make_float4(flo.x, flo.y, fhi.x, fhi.y);
}

__global__ void __launch_bounds__(256) k_gather(const __half* __restrict__ h,
                                                const float* __restrict__ b,
                                                __half* __restrict__ out) {
    int gt = blockIdx.x * blockDim.x + threadIdx.x;
    int node = gt >> 4;
    int c = gt & 15;
    if (node >= N_NODES) return;

    const uint2* h2 = (const uint2*)h;
    float4 acc = h4_to_f4(h2[(size_t)node * 16 + c]);   // self loop (pre-scaled)

    int e0 = g_rowstart[node];
    int e1 = g_rowstart[node + 1];
    int e = e0;
    // 2-way unroll for MLP
    for (; e + 1 < e1; e += 2) {
        int s0 = g_csrc[e];
        int s1 = g_csrc[e + 1];
        float4 v0 = h4_to_f4(h2[(size_t)s0 * 16 + c]);
        float4 v1 = h4_to_f4(h2[(size_t)s1 * 16 + c]);
        acc.x += v0.x + v1.x;
        acc.y += v0.y + v1.y;
        acc.z += v0.z + v1.z;
        acc.w += v0.w + v1.w;
    }
    if (e < e1) {
        float4 v = h4_to_f4(h2[(size_t)g_csrc[e] * 16 + c]);
        acc.x += v.x; acc.y += v.y; acc.z += v.z; acc.w += v.w;
    }

    float di = g_dinv[node];
    float4 bb = ((const float4*)b)[c];
    float o0 = fmaxf(acc.x * di + bb.x, 0.f);
    float o1 = fmaxf(acc.y * di + bb.y, 0.f);
    float o2 = fmaxf(acc.z * di + bb.z, 0.f);
    float o3 = fmaxf(acc.w * di + bb.w, 0.f);
    __half2 plo = __floats2half2_rn(o0, o1);
    __half2 phi = __floats2half2_rn(o2, o3);
    uint2 u;
    u.x = *(unsigned*)&plo;
    u.y = *(unsigned*)&phi;
    ((uint2*)out)[(size_t)node * 16 + c] = u;
}

// ------- pool: per-node dot with fc_w, scalar atomic into per-graph sum -----
__global__ void __launch_bounds__(256) k_pool(const __half* __restrict__ hfin,
                                              const float* __restrict__ fcw,
                                              const int* __restrict__ batch) {
    __shared__ float w[D];
    if (threadIdx.x < D) w[threadIdx.x] = fcw[threadIdx.x];
    __syncthreads();
    int i = blockIdx.x * blockDim.x + threadIdx.x;
    if (i >= N_NODES) return;
    const uint2* r = (const uint2*)(hfin + (size_t)i * D);
    float s = 0.f;
#pragma unroll
    for (int c = 0; c < 16; c++) {
        float4 v = h4_to_f4(r[c]);
        s += v.x * w[c * 4 + 0] + v.y * w[c * 4 + 1]
           + v.z * w[c * 4 + 2] + v.w * w[c * 4 + 3];
    }
    atomicAdd(&g_gsum[batch[i]], s);
}

__global__ void k_final(float* __restrict__ out, const float* __restrict__ fcb) {
    int g = blockIdx.x * blockDim.x + threadIdx.x;
    if (g < N_GRAPHS)
        out[g] = g_gsum[g] / fmaxf((float)g_gcnt[g], 1.f) + fcb[0];
}

// ---------------- launch ------------------------------------------------------
extern "C" void kernel_launch(void* const* d_in, const int* in_sizes, int n_in,
                              void* d_out, int out_size) {
    const float* x     = (const float*)d_in[0];
    const int*   ei    = (const int*)  d_in[1];
    const int*   batch = (const int*)  d_in[2];
    const float* w0    = (const float*)d_in[3];
    const float* b0    = (const float*)d_in[4];
    const float* w1    = (const float*)d_in[5];
    const float* b1    = (const float*)d_in[6];
    const float* w2    = (const float*)d_in[7];
    const float* b2    = (const float*)d_in[8];
    const float* fcw   = (const float*)d_in[9];
    const float* fcb   = (const float*)d_in[10];
    float* out = (float*)d_out;

    __half *h, *t0, *t1;
    cudaGetSymbolAddress((void**)&h,  g_h);
    cudaGetSymbolAddress((void**)&t0, g_t0);
    cudaGetSymbolAddress((void**)&t1, g_t1);

    const int TB = 256;
    int nb_nodes = (N_NODES + TB - 1) / TB;       // 391
    int nb_edges = (N_EDGES + TB - 1) / TB;       // 5000
    int nb_gemm  = (N_NODES + 127) / 128;         // 782
    int nb_gath  = (N_NODES * 16 + TB - 1) / TB;  // 6250

    // CSR build (once per call, reused by all 3 layers)
    k_zero <<<nb_nodes, TB>>>();
    k_deg  <<<nb_edges, TB>>>(ei);
    k_scan1<<<N_SCANBLK, SCAN_B>>>();
    k_scan2<<<1, 32>>>();
    k_scan3<<<nb_nodes, TB>>>(batch);
    k_fill <<<nb_edges, TB>>>(ei);

    // layer 1
    k_gemm<float> <<<nb_gemm, 128>>>(x, w0, h);
    k_gather      <<<nb_gath, TB>>>(h, b0, t0);
    // layer 2
    k_gemm<__half><<<nb_gemm, 128>>>(t0, w1, h);
    k_gather      <<<nb_gath, TB>>>(h, b1, t1);
    // layer 3
    k_gemm<__half><<<nb_gemm, 128>>>(t1, w2, h);
    k_gather      <<<nb_gath, TB>>>(h, b2, t0);

    // pool + head
    k_pool <<<nb_nodes, TB>>>(t0, fcw, batch);
    k_final<<<(N_GRAPHS + TB - 1) / TB, TB>>>(out, fcb);
}

// round 3
// speedup vs baseline: 1.5617x; 1.3424x over previous
#include <cuda_runtime.h>
#include <cuda_fp16.h>
#include <mma.h>
using namespace nvcuda;

#define N_NODES   100000
#define N_EDGES   1280000
#define D         64
#define N_GRAPHS  512
#define SCAN_B    1024
#define N_SCANBLK ((N_NODES + SCAN_B - 1) / SCAN_B)   // 98

// ---------------- scratch (device globals; no cudaMalloc allowed) -----------
__device__ __half g_h  [N_NODES * D];   // GEMM output, pre-scaled by dinv[row]
__device__ __half g_t0 [N_NODES * D];
__device__ __half g_t1 [N_NODES * D];
__device__ float  g_dinv[N_NODES];
__device__ int    g_dege[N_NODES];
__device__ int    g_rowstart[N_NODES + 1];
__device__ int    g_cursor[N_NODES];
__device__ int    g_bsums[128];
__device__ int    g_csrc [N_EDGES];
__device__ float  g_gsum[N_GRAPHS];
__device__ int    g_gcnt[N_GRAPHS];

// ---------------- setup kernels ---------------------------------------------
__global__ void k_deg(const int* __restrict__ ei) {
    int e = blockIdx.x * blockDim.x + threadIdx.x;
    if (e < N_EDGES) atomicAdd(&g_dege[ei[N_EDGES + e]], 1);
}

__global__ void k_scan1() {
    __shared__ int sh[SCAN_B];
    int tid = threadIdx.x;
    int i = blockIdx.x * SCAN_B + tid;
    int v = (i < N_NODES) ? g_dege[i] : 0;
    sh[tid] = v;
    __syncthreads();
    for (int off = 1; off < SCAN_B; off <<= 1) {
        int t = 0;
        if (tid >= off) t = sh[tid - off];
        __syncthreads();
        sh[tid] += t;
        __syncthreads();
    }
    int incl = sh[tid];
    if (i < N_NODES) g_rowstart[i] = incl - v;   // exclusive
    if (tid == SCAN_B - 1) g_bsums[blockIdx.x] = incl;
}

// parallel exclusive scan over the 98 block sums (single 128-thread block)
__global__ void k_scan2() {
    __shared__ int sh[128];
    int tid = threadIdx.x;
    int v = (tid < N_SCANBLK) ? g_bsums[tid] : 0;
    sh[tid] = v;
    __syncthreads();
    for (int off = 1; off < 128; off <<= 1) {
        int t = 0;
        if (tid >= off) t = sh[tid - off];
        __syncthreads();
        sh[tid] += t;
        __syncthreads();
    }
    if (tid < N_SCANBLK) g_bsums[tid] = sh[tid] - v;   // exclusive
    if (tid == N_SCANBLK - 1) g_rowstart[N_NODES] = sh[tid];
}

__global__ void k_scan3(const int* __restrict__ batch) {
    int i = blockIdx.x * blockDim.x + threadIdx.x;
    if (i < N_NODES) {
        int rs = g_rowstart[i] + g_bsums[i / SCAN_B];
        g_rowstart[i] = rs;
        g_cursor[i] = rs;
        g_dinv[i] = rsqrtf((float)(g_dege[i] + 1));   // +1 self loop
        atomicAdd(&g_gcnt[batch[i]], 1);
    }
}

__global__ void k_fill(const int* __restrict__ ei) {
    int e = blockIdx.x * blockDim.x + threadIdx.x;
    if (e < N_EDGES) {
        int s = ei[e];
        int d = ei[N_EDGES + e];
        int pos = atomicAdd(&g_cursor[d], 1);
        g_csrc[pos] = s;
    }
}

// ---------------- tensor-core GEMM: out[row] = dinv[row]*(in[row] @ W), fp16 out
// Block = 128 threads (4 warps) -> 64 rows. N_NODES % 16 == 0, so warp tiles
// are always full; warps with row0 >= N skip.
#define LDW 72   // padded leading dim (halves / floats) to dodge smem bank conflicts

__device__ __forceinline__ void load_weights_sh(__half* wsh, const float* __restrict__ W, int tid) {
    for (int i = tid; i < D * D; i += 128) {
        int r = i >> 6, c = i & 63;
        wsh[r * LDW + c] = __float2half(W[i]);
    }
}

__device__ __forceinline__ void gemm_epilogue(const float* osh, __half* __restrict__ out,
                                              int blockRow0, int tid) {
    int r = tid >> 1;
    int cbase = (tid & 1) * 32;
    int row = blockRow0 + r;
    if (row >= N_NODES) return;
    float s = g_dinv[row];
    uint4* orow = (uint4*)(out + (size_t)row * D + cbase);
    const float* src = osh + r * LDW + cbase;
#pragma unroll
    for (int q = 0; q < 4; q++) {
        __half2 p0 = __floats2half2_rn(src[q * 8 + 0] * s, src[q * 8 + 1] * s);
        __half2 p1 = __floats2half2_rn(src[q * 8 + 2] * s, src[q * 8 + 3] * s);
        __half2 p2 = __floats2half2_rn(src[q * 8 + 4] * s, src[q * 8 + 5] * s);
        __half2 p3 = __floats2half2_rn(src[q * 8 + 6] * s, src[q * 8 + 7] * s);
        uint4 u;
        u.x = *(unsigned*)&p0; u.y = *(unsigned*)&p1;
        u.z = *(unsigned*)&p2; u.w = *(unsigned*)&p3;
        orow[q] = u;
    }
}

__global__ void __launch_bounds__(128) k_gemm_f16(const __half* __restrict__ in,
                                                  const float* __restrict__ W,
                                                  __half* __restrict__ out) {
    __shared__ __half wsh[D * LDW];
    __shared__ float  osh[D * LDW];
    int tid = threadIdx.x;
    load_weights_sh(wsh, W, tid);
    __syncthreads();

    int warp = tid >> 5;
    int row0 = blockIdx.x * 64 + warp * 16;
    if (row0 < N_NODES) {
        wmma::fragment<wmma::accumulator, 16, 16, 16, float> acc[4];
#pragma unroll
        for (int n = 0; n < 4; n++) wmma::fill_fragment(acc[n], 0.0f);
#pragma unroll
        for (int k = 0; k < 4; k++) {
            wmma::fragment<wmma::matrix_a, 16, 16, 16, __half, wmma::row_major> a;
            wmma::load_matrix_sync(a, in + (size_t)row0 * D + k * 16, D);
#pragma unroll
            for (int n = 0; n < 4; n++) {
                wmma::fragment<wmma::matrix_b, 16, 16, 16, __half, wmma::row_major> b;
                wmma::load_matrix_sync(b, wsh + (k * 16) * LDW + n * 16, LDW);
                wmma::mma_sync(acc[n], a, b, acc[n]);
            }
        }
#pragma unroll
        for (int n = 0; n < 4; n++)
            wmma::store_matrix_sync(osh + (warp * 16) * LDW + n * 16, acc[n], LDW, wmma::mem_row_major);
    }
    __syncthreads();
    gemm_epilogue(osh, out, blockIdx.x * 64, tid);
}

__global__ void __launch_bounds__(128) k_gemm_f32(const float* __restrict__ in,
                                                  const float* __restrict__ W,
                                                  __half* __restrict__ out) {
    __shared__ __half wsh[D * LDW];
    __shared__ __half ash[D * LDW];
    __shared__ float  osh[D * LDW];
    int tid = threadIdx.x;
    load_weights_sh(wsh, W, tid);
    // stage & convert this block's 64 input rows to fp16
    for (int i = tid; i < D * D; i += 128) {
        int r = i >> 6, c = i & 63;
        int row = blockIdx.x * 64 + r;
        float v = (row < N_NODES) ? in[(size_t)row * D + c] : 0.f;
        ash[r * LDW + c] = __float2half(v);
    }
    __syncthreads();

    int warp = tid >> 5;
    int row0 = blockIdx.x * 64 + warp * 16;
    if (row0 < N_NODES) {
        wmma::fragment<wmma::accumulator, 16, 16, 16, float> acc[4];
#pragma unroll
        for (int n = 0; n < 4; n++) wmma::fill_fragment(acc[n], 0.0f);
#pragma unroll
        for (int k = 0; k < 4; k++) {
            wmma::fragment<wmma::matrix_a, 16, 16, 16, __half, wmma::row_major> a;
            wmma::load_matrix_sync(a, ash + (warp * 16) * LDW + k * 16, LDW);
#pragma unroll
            for (int n = 0; n < 4; n++) {
                wmma::fragment<wmma::matrix_b, 16, 16, 16, __half, wmma::row_major> b;
                wmma::load_matrix_sync(b, wsh + (k * 16) * LDW + n * 16, LDW);
                wmma::mma_sync(acc[n], a, b, acc[n]);
            }
        }
#pragma unroll
        for (int n = 0; n < 4; n++)
            wmma::store_matrix_sync(osh + (warp * 16) * LDW + n * 16, acc[n], LDW, wmma::mem_row_major);
    }
    __syncthreads();
    gemm_epilogue(osh, out, blockIdx.x * 64, tid);
}

// ------- gather: out = relu( dinv_n * (sum_{e: dst=n} h'[src_e] + h'[n]) + b )
__device__ __forceinline__ float4 h4_to_f4(uint2 v) {
    __half2 lo = *(__half2*)&v.x;
    __half2 hi = *(__half2*)&v.y;
    float2 flo = __half22float2(lo);
    float2 fhi = __half22float2(hi);
    return make_float4(flo.x, flo.y, fhi.x, fhi.y);
}

__global__ void __launch_bounds__(256) k_gather(const __half* __restrict__ h,
                                                const float* __restrict__ b,
                                                __half* __restrict__ out) {
    int gt = blockIdx.x * blockDim.x + threadIdx.x;
    int node = gt >> 4;
    int c = gt & 15;
    if (node >= N_NODES) return;

    const uint2* h2 = (const uint2*)h;
    float4 acc = h4_to_f4(h2[(size_t)node * 16 + c]);   // self loop (pre-scaled)

    int e0 = g_rowstart[node];
    int e1 = g_rowstart[node + 1];
    int e = e0;
    for (; e + 3 < e1; e += 4) {
        int s0 = g_csrc[e];
        int s1 = g_csrc[e + 1];
        int s2 = g_csrc[e + 2];
        int s3 = g_csrc[e + 3];
        float4 v0 = h4_to_f4(h2[(size_t)s0 * 16 + c]);
        float4 v1 = h4_to_f4(h2[(size_t)s1 * 16 + c]);
        float4 v2 = h4_to_f4(h2[(size_t)s2 * 16 + c]);
        float4 v3 = h4_to_f4(h2[(size_t)s3 * 16 + c]);
        acc.x += (v0.x + v1.x) + (v2.x + v3.x);
        acc.y += (v0.y + v1.y) + (v2.y + v3.y);
        acc.z += (v0.z + v1.z) + (v2.z + v3.z);
        acc.w += (v0.w + v1.w) + (v2.w + v3.w);
    }
    for (; e < e1; e++) {
        float4 v = h4_to_f4(h2[(size_t)g_csrc[e] * 16 + c]);
        acc.x += v.x; acc.y += v.y; acc.z += v.z; acc.w += v.w;
    }

    float di = g_dinv[node];
    float4 bb = ((const float4*)b)[c];
    float o0 = fmaxf(acc.x * di + bb.x, 0.f);
    float o1 = fmaxf(acc.y * di + bb.y, 0.f);
    float o2 = fmaxf(acc.z * di + bb.z, 0.f);
    float o3 = fmaxf(acc.w * di + bb.w, 0.f);
    __half2 plo = __floats2half2_rn(o0, o1);
    __half2 phi = __floats2half2_rn(o2, o3);
    uint2 u;
    u.x = *(unsigned*)&plo;
    u.y = *(unsigned*)&phi;
    ((uint2*)out)[(size_t)node * 16 + c] = u;
}

// ------- pool + head ---------------------------------------------------------
__global__ void __launch_bounds__(256) k_pool(const __half* __restrict__ hfin,
                                              const float* __restrict__ fcw,
                                              const int* __restrict__ batch) {
    __shared__ float w[D];
    if (threadIdx.x < D) w[threadIdx.x] = fcw[threadIdx.x];
    __syncthreads();
    int i = blockIdx.x * blockDim.x + threadIdx.x;
    if (i >= N_NODES) return;
    const uint2* r = (const uint2*)(hfin + (size_t)i * D);
    float s = 0.f;
#pragma unroll
    for (int c = 0; c < 16; c++) {
        float4 v = h4_to_f4(r[c]);
        s += v.x * w[c * 4 + 0] + v.y * w[c * 4 + 1]
           + v.z * w[c * 4 + 2] + v.w * w[c * 4 + 3];
    }
    atomicAdd(&g_gsum[batch[i]], s);
}

__global__ void k_final(float* __restrict__ out, const float* __restrict__ fcb) {
    int g = blockIdx.x * blockDim.x + threadIdx.x;
    if (g < N_GRAPHS)
        out[g] = g_gsum[g] / fmaxf((float)g_gcnt[g], 1.f) + fcb[0];
}

// ---------------- launch ------------------------------------------------------
extern "C" void kernel_launch(void* const* d_in, const int* in_sizes, int n_in,
                              void* d_out, int out_size) {
    const float* x     = (const float*)d_in[0];
    const int*   ei    = (const int*)  d_in[1];
    const int*   batch = (const int*)  d_in[2];
    const float* w0    = (const float*)d_in[3];
    const float* b0    = (const float*)d_in[4];
    const float* w1    = (const float*)d_in[5];
    const float* b1    = (const float*)d_in[6];
    const float* w2    = (const float*)d_in[7];
    const float* b2    = (const float*)d_in[8];
    const float* fcw   = (const float*)d_in[9];
    const float* fcb   = (const float*)d_in[10];
    float* out = (float*)d_out;

    __half *h, *t0, *t1;
    void *p_dege, *p_gsum, *p_gcnt;
    cudaGetSymbolAddress((void**)&h,  g_h);
    cudaGetSymbolAddress((void**)&t0, g_t0);
    cudaGetSymbolAddress((void**)&t1, g_t1);
    cudaGetSymbolAddress(&p_dege, g_dege);
    cudaGetSymbolAddress(&p_gsum, g_gsum);
    cudaGetSymbolAddress(&p_gcnt, g_gcnt);

    const int TB = 256;
    int nb_nodes = (N_NODES + TB - 1) / TB;       // 391
    int nb_edges = (N_EDGES + TB - 1) / TB;       // 5000
    int nb_gemm  = (N_NODES + 63) / 64;           // 1563
    int nb_gath  = (N_NODES * 16 + TB - 1) / TB;  // 6250

    // zero scratch (memset nodes are graph-capturable)
    cudaMemsetAsync(p_dege, 0, N_NODES * sizeof(int));
    cudaMemsetAsync(p_gsum, 0, N_GRAPHS * sizeof(float));
    cudaMemsetAsync(p_gcnt, 0, N_GRAPHS * sizeof(int));

    // CSR build (once per call, reused by all 3 layers)
    k_deg  <<<nb_edges, TB>>>(ei);
    k_scan1<<<N_SCANBLK, SCAN_B>>>();
    k_scan2<<<1, 128>>>();
    k_scan3<<<nb_nodes, TB>>>(batch);
    k_fill <<<nb_edges, TB>>>(ei);

    // layer 1
    k_gemm_f32<<<nb_gemm, 128>>>(x, w0, h);
    k_gather  <<<nb_gath, TB>>>(h, b0, t0);
    // layer 2
    k_gemm_f16<<<nb_gemm, 128>>>(t0, w1, h);
    k_gather  <<<nb_gath, TB>>>(h, b1, t1);
    // layer 3
    k_gemm_f16<<<nb_gemm, 128>>>(t1, w2, h);
    k_gather  <<<nb_gath, TB>>>(h, b2, t0);

    // pool + head
    k_pool <<<nb_nodes, TB>>>(t0, fcw, batch);
    k_final<<<(N_GRAPHS + TB - 1) / TB, TB>>>(out, fcb);
}

// round 4
// speedup vs baseline: 1.8277x; 1.1703x over previous
#include <cuda_runtime.h>
#include <cuda_fp16.h>
#include <mma.h>
using namespace nvcuda;

#define N_NODES   100000
#define N_EDGES   1280000
#define D         64
#define N_GRAPHS  512
#define SCAN_B    1024
#define N_SCANBLK ((N_NODES + SCAN_B - 1) / SCAN_B)   // 98

// ---------------- scratch (device globals; no cudaMalloc allowed) -----------
__device__ __half g_h  [N_NODES * D];   // GEMM output, pre-scaled by dinv[row]
__device__ __half g_t0 [N_NODES * D];
__device__ __half g_t1 [N_NODES * D];
__device__ float  g_dinv[N_NODES];
__device__ int    g_dege[N_NODES];
__device__ int    g_rowstart[N_NODES + 1];
__device__ int    g_cursor[N_NODES];
__device__ int    g_bsums[128];
__device__ int    g_csrc [N_EDGES];

// ---------------- setup kernels ---------------------------------------------
__global__ void k_deg(const int* __restrict__ ei) {
    int e = blockIdx.x * blockDim.x + threadIdx.x;
    if (e < N_EDGES) atomicAdd(&g_dege[ei[N_EDGES + e]], 1);
}

__global__ void k_scan1() {
    __shared__ int sh[SCAN_B];
    int tid = threadIdx.x;
    int i = blockIdx.x * SCAN_B + tid;
    int v = (i < N_NODES) ? g_dege[i] : 0;
    sh[tid] = v;
    __syncthreads();
    for (int off = 1; off < SCAN_B; off <<= 1) {
        int t = 0;
        if (tid >= off) t = sh[tid - off];
        __syncthreads();
        sh[tid] += t;
        __syncthreads();
    }
    int incl = sh[tid];
    if (i < N_NODES) g_rowstart[i] = incl - v;   // exclusive
    if (tid == SCAN_B - 1) g_bsums[blockIdx.x] = incl;
}

// parallel exclusive scan over the 98 block sums (single 128-thread block)
__global__ void k_scan2() {
    __shared__ int sh[128];
    int tid = threadIdx.x;
    int v = (tid < N_SCANBLK) ? g_bsums[tid] : 0;
    sh[tid] = v;
    __syncthreads();
    for (int off = 1; off < 128; off <<= 1) {
        int t = 0;
        if (tid >= off) t = sh[tid - off];
        __syncthreads();
        sh[tid] += t;
        __syncthreads();
    }
    if (tid < N_SCANBLK) g_bsums[tid] = sh[tid] - v;   // exclusive
    if (tid == N_SCANBLK - 1) g_rowstart[N_NODES] = sh[tid];
}

__global__ void k_scan3() {
    int i = blockIdx.x * blockDim.x + threadIdx.x;
    if (i < N_NODES) {
        int rs = g_rowstart[i] + g_bsums[i / SCAN_B];
        g_rowstart[i] = rs;
        g_cursor[i] = rs;
        g_dinv[i] = rsqrtf((float)(g_dege[i] + 1));   // +1 self loop
    }
}

__global__ void k_fill(const int* __restrict__ ei) {
    int e = blockIdx.x * blockDim.x + threadIdx.x;
    if (e < N_EDGES) {
        int s = ei[e];
        int d = ei[N_EDGES + e];
        int pos = atomicAdd(&g_cursor[d], 1);
        g_csrc[pos] = s;
    }
}

// ---------------- tensor-core GEMM: out[row] = dinv[row]*(in[row] @ W), fp16 out
#define LDW 72   // padded leading dim to dodge smem bank conflicts

__device__ __forceinline__ void load_weights_sh(__half* wsh, const float* __restrict__ W, int tid) {
    for (int i = tid; i < D * D; i += 128) {
        int r = i >> 6, c = i & 63;
        wsh[r * LDW + c] = __float2half(W[i]);
    }
}

__device__ __forceinline__ void gemm_epilogue(const float* osh, __half* __restrict__ out,
                                              int blockRow0, int tid) {
    int r = tid >> 1;
    int cbase = (tid & 1) * 32;
    int row = blockRow0 + r;
    if (row >= N_NODES) return;
    float s = g_dinv[row];
    uint4* orow = (uint4*)(out + (size_t)row * D + cbase);
    const float* src = osh + r * LDW + cbase;
#pragma unroll
    for (int q = 0; q < 4; q++) {
        __half2 p0 = __floats2half2_rn(src[q * 8 + 0] * s, src[q * 8 + 1] * s);
        __half2 p1 = __floats2half2_rn(src[q * 8 + 2] * s, src[q * 8 + 3] * s);
        __half2 p2 = __floats2half2_rn(src[q * 8 + 4] * s, src[q * 8 + 5] * s);
        __half2 p3 = __floats2half2_rn(src[q * 8 + 6] * s, src[q * 8 + 7] * s);
        uint4 u;
        u.x = *(unsigned*)&p0; u.y = *(unsigned*)&p1;
        u.z = *(unsigned*)&p2; u.w = *(unsigned*)&p3;
        orow[q] = u;
    }
}

__global__ void __launch_bounds__(128) k_gemm_f16(const __half* __restrict__ in,
                                                  const float* __restrict__ W,
                                                  __half* __restrict__ out) {
    __shared__ __half wsh[D * LDW];
    __shared__ float  osh[D * LDW];
    int tid = threadIdx.x;
    load_weights_sh(wsh, W, tid);
    __syncthreads();

    int warp = tid >> 5;
    int row0 = blockIdx.x * 64 + warp * 16;
    if (row0 < N_NODES) {
        wmma::fragment<wmma::accumulator, 16, 16, 16, float> acc[4];
#pragma unroll
        for (int n = 0; n < 4; n++) wmma::fill_fragment(acc[n], 0.0f);
#pragma unroll
        for (int k = 0; k < 4; k++) {
            wmma::fragment<wmma::matrix_a, 16, 16, 16, __half, wmma::row_major> a;
            wmma::load_matrix_sync(a, in + (size_t)row0 * D + k * 16, D);
#pragma unroll
            for (int n = 0; n < 4; n++) {
                wmma::fragment<wmma::matrix_b, 16, 16, 16, __half, wmma::row_major> b;
                wmma::load_matrix_sync(b, wsh + (k * 16) * LDW + n * 16, LDW);
                wmma::mma_sync(acc[n], a, b, acc[n]);
            }
        }
#pragma unroll
        for (int n = 0; n < 4; n++)
            wmma::store_matrix_sync(osh + (warp * 16) * LDW + n * 16, acc[n], LDW, wmma::mem_row_major);
    }
    __syncthreads();
    gemm_epilogue(osh, out, blockIdx.x * 64, tid);
}

__global__ void __launch_bounds__(128) k_gemm_f32(const float* __restrict__ in,
                                                  const float* __restrict__ W,
                                                  __half* __restrict__ out) {
    __shared__ __half wsh[D * LDW];
    __shared__ __half ash[D * LDW];
    __shared__ float  osh[D * LDW];
    int tid = threadIdx.x;
    load_weights_sh(wsh, W, tid);
    // stage & convert this block's 64 input rows to fp16
    for (int i = tid; i < D * D; i += 128) {
        int r = i >> 6, c = i & 63;
        int row = blockIdx.x * 64 + r;
        float v = (row < N_NODES) ? in[(size_t)row * D + c] : 0.f;
        ash[r * LDW + c] = __float2half(v);
    }
    __syncthreads();

    int warp = tid >> 5;
    int row0 = blockIdx.x * 64 + warp * 16;
    if (row0 < N_NODES) {
        wmma::fragment<wmma::accumulator, 16, 16, 16, float> acc[4];
#pragma unroll
        for (int n = 0; n < 4; n++) wmma::fill_fragment(acc[n], 0.0f);
#pragma unroll
        for (int k = 0; k < 4; k++) {
            wmma::fragment<wmma::matrix_a, 16, 16, 16, __half, wmma::row_major> a;
            wmma::load_matrix_sync(a, ash + (warp * 16) * LDW + k * 16, LDW);
#pragma unroll
            for (int n = 0; n < 4; n++) {
                wmma::fragment<wmma::matrix_b, 16, 16, 16, __half, wmma::row_major> b;
                wmma::load_matrix_sync(b, wsh + (k * 16) * LDW + n * 16, LDW);
                wmma::mma_sync(acc[n], a, b, acc[n]);
            }
        }
#pragma unroll
        for (int n = 0; n < 4; n++)
            wmma::store_matrix_sync(osh + (warp * 16) * LDW + n * 16, acc[n], LDW, wmma::mem_row_major);
    }
    __syncthreads();
    gemm_epilogue(osh, out, blockIdx.x * 64, tid);
}

// ------- gather: out = relu( dinv_n * (sum_{e: dst=n} h'[src_e] + h'[n]) + b )
__device__ __forceinline__ float4 h4_to_f4(uint2 v) {
    __half2 lo = *(__half2*)&v.x;
    __half2 hi = *(__half2*)&v.y;
    float2 flo = __half22float2(lo);
    float2 fhi = __half22float2(hi);
    return make_float4(flo.x, flo.y, fhi.x, fhi.y);
}

__global__ void __launch_bounds__(256) k_gather(const __half* __restrict__ h,
                                                const float* __restrict__ b,
                                                __half* __restrict__ out) {
    int gt = blockIdx.x * blockDim.x + threadIdx.x;
    int node = gt >> 4;
    int c = gt & 15;
    if (node >= N_NODES) return;

    const uint2* h2 = (const uint2*)h;
    float4 acc = h4_to_f4(h2[(size_t)node * 16 + c]);   // self loop (pre-scaled)

    int e0 = g_rowstart[node];
    int e1 = g_rowstart[node + 1];
    int e = e0;
    for (; e + 3 < e1; e += 4) {
        int s0 = g_csrc[e];
        int s1 = g_csrc[e + 1];
        int s2 = g_csrc[e + 2];
        int s3 = g_csrc[e + 3];
        float4 v0 = h4_to_f4(h2[(size_t)s0 * 16 + c]);
        float4 v1 = h4_to_f4(h2[(size_t)s1 * 16 + c]);
        float4 v2 = h4_to_f4(h2[(size_t)s2 * 16 + c]);
        float4 v3 = h4_to_f4(h2[(size_t)s3 * 16 + c]);
        acc.x += (v0.x + v1.x) + (v2.x + v3.x);
        acc.y += (v0.y + v1.y) + (v2.y + v3.y);
        acc.z += (v0.z + v1.z) + (v2.z + v3.z);
        acc.w += (v0.w + v1.w) + (v2.w + v3.w);
    }
    for (; e < e1; e++) {
        float4 v = h4_to_f4(h2[(size_t)g_csrc[e] * 16 + c]);
        acc.x += v.x; acc.y += v.y; acc.z += v.z; acc.w += v.w;
    }

    float di = g_dinv[node];
    float4 bb = ((const float4*)b)[c];
    float o0 = fmaxf(acc.x * di + bb.x, 0.f);
    float o1 = fmaxf(acc.y * di + bb.y, 0.f);
    float o2 = fmaxf(acc.z * di + bb.z, 0.f);
    float o3 = fmaxf(acc.w * di + bb.w, 0.f);
    __half2 plo = __floats2half2_rn(o0, o1);
    __half2 phi = __floats2half2_rn(o2, o3);
    uint2 u;
    u.x = *(unsigned*)&plo;
    u.y = *(unsigned*)&phi;
    ((uint2*)out)[(size_t)node * 16 + c] = u;
}

// ------- pool + head: one block per graph, zero atomics ----------------------
// batch is sorted; block g binary-searches its [start,end) node range,
// computes mean(h) . fcw + fcb directly.
__global__ void __launch_bounds__(256) k_pool_graph(const __half* __restrict__ hfin,
                                                    const float* __restrict__ fcw,
                                                    const float* __restrict__ fcb,
                                                    const int* __restrict__ batch,
                                                    float* __restrict__ out) {
    __shared__ float w[D];
    __shared__ int bounds[2];
    __shared__ float red[256 / 32];

    int tid = threadIdx.x;
    int g = blockIdx.x;
    if (tid < D) w[tid] = fcw[tid];
    if (tid == 0 || tid == 1) {
        // lower_bound of g (tid 0) / lower_bound of g+1 (tid 1)
        int key = g + tid;
        int lo = 0, hi = N_NODES;
        while (lo < hi) {
            int mid = (lo + hi) >> 1;
            if (batch[mid] < key) lo = mid + 1; else hi = mid;
        }
        bounds[tid] = lo;
    }
    __syncthreads();
    int start = bounds[0], end = bounds[1];

    float s = 0.f;
    for (int i = start + tid; i < end; i += 256) {
        const uint2* r = (const uint2*)(hfin + (size_t)i * D);
        float t = 0.f;
#pragma unroll
        for (int c = 0; c < 16; c++) {
            float4 v = h4_to_f4(r[c]);
            t += v.x * w[c * 4 + 0] + v.y * w[c * 4 + 1]
               + v.z * w[c * 4 + 2] + v.w * w[c * 4 + 3];
        }
        s += t;
    }
    // block reduce
#pragma unroll
    for (int off = 16; off > 0; off >>= 1)
        s += __shfl_down_sync(0xffffffffu, s, off);
    if ((tid & 31) == 0) red[tid >> 5] = s;
    __syncthreads();
    if (tid == 0) {
        float tot = 0.f;
#pragma unroll
        for (int wi = 0; wi < 256 / 32; wi++) tot += red[wi];
        int cnt = end - start;
        out[g] = tot / fmaxf((float)cnt, 1.f) + fcb[0];
    }
}

// ---------------- launch ------------------------------------------------------
extern "C" void kernel_launch(void* const* d_in, const int* in_sizes, int n_in,
                              void* d_out, int out_size) {
    const float* x     = (const float*)d_in[0];
    const int*   ei    = (const int*)  d_in[1];
    const int*   batch = (const int*)  d_in[2];
    const float* w0    = (const float*)d_in[3];
    const float* b0    = (const float*)d_in[4];
    const float* w1    = (const float*)d_in[5];
    const float* b1    = (const float*)d_in[6];
    const float* w2    = (const float*)d_in[7];
    const float* b2    = (const float*)d_in[8];
    const float* fcw   = (const float*)d_in[9];
    const float* fcb   = (const float*)d_in[10];
    float* out = (float*)d_out;

    __half *h, *t0, *t1;
    void *p_dege;
    cudaGetSymbolAddress((void**)&h,  g_h);
    cudaGetSymbolAddress((void**)&t0, g_t0);
    cudaGetSymbolAddress((void**)&t1, g_t1);
    cudaGetSymbolAddress(&p_dege, g_dege);

    const int TB = 256;
    int nb_nodes = (N_NODES + TB - 1) / TB;       // 391
    int nb_edges = (N_EDGES + TB - 1) / TB;       // 5000
    int nb_gemm  = (N_NODES + 63) / 64;           // 1563
    int nb_gath  = (N_NODES * 16 + TB - 1) / TB;  // 6250

    cudaMemsetAsync(p_dege, 0, N_NODES * sizeof(int));

    // CSR build (once per call, reused by all 3 layers)
    k_deg  <<<nb_edges, TB>>>(ei);
    k_scan1<<<N_SCANBLK, SCAN_B>>>();
    k_scan2<<<1, 128>>>();
    k_scan3<<<nb_nodes, TB>>>();
    k_fill <<<nb_edges, TB>>>(ei);

    // layer 1
    k_gemm_f32<<<nb_gemm, 128>>>(x, w0, h);
    k_gather  <<<nb_gath, TB>>>(h, b0, t0);
    // layer 2
    k_gemm_f16<<<nb_gemm, 128>>>(t0, w1, h);
    k_gather  <<<nb_gath, TB>>>(h, b1, t1);
    // layer 3
    k_gemm_f16<<<nb_gemm, 128>>>(t1, w2, h);
    k_gather  <<<nb_gath, TB>>>(h, b2, t0);

    // pool + head (fused, no atomics)
    k_pool_graph<<<N_GRAPHS, 256>>>(t0, fcw, fcb, batch, out);
}